// round 1
// baseline (speedup 1.0000x reference)
#include <cuda_runtime.h>
#include <math.h>

// Problem constants
#define NB 8
#define NC 16
#define ND 64
#define NH 64
#define NW 64
#define NR 32
#define NBC 128          // B*C
#define EPSV 1e-5f

// ---------------------------------------------------------------------------
// Scratch (device globals; no allocation allowed). Re-zeroed each launch.
// ---------------------------------------------------------------------------
__device__ float g_S1[NBC * ND];   // sum over (h,w) per (bc,d)
__device__ float g_S2[NBC * NH];   // sum over (d,w) per (bc,h)
__device__ float g_S3[NBC * NW];   // sum over (d,h) per (bc,w)
__device__ float g_SSQ[NC];        // sum of x^2 per channel
__device__ float g_W2[NH * NR];    // W2[h*32+r] = mean_s core2[r][h][s]

// ---------------------------------------------------------------------------
// Kernel 0: zero scratch + precompute W2 from core2 (256 KB read, once)
// zero count = 8192*3 + 16 = 24592 ; W2 count = 2048 ; total 26640
// ---------------------------------------------------------------------------
__global__ void prep_kernel(const float* __restrict__ core2) {
    int idx = blockIdx.x * 256 + threadIdx.x;
    if (idx < 8192)        g_S1[idx] = 0.f;
    else if (idx < 16384)  g_S2[idx - 8192] = 0.f;
    else if (idx < 24576)  g_S3[idx - 16384] = 0.f;
    else if (idx < 24592)  g_SSQ[idx - 24576] = 0.f;
    else if (idx < 26640) {
        int t = idx - 24592;          // t = h*32 + r
        int h = t >> 5, r = t & 31;
        const float4* p = (const float4*)(core2 + (size_t)(r * NH + h) * NR);
        float s = 0.f;
#pragma unroll
        for (int k = 0; k < 8; k++) { float4 v = p[k]; s += (v.x + v.y) + (v.z + v.w); }
        g_W2[t] = s * (1.0f / NR);
    }
}

// ---------------------------------------------------------------------------
// Kernel 1: the single pass over x (134 MB). Memory-bound.
// grid = (16 chunks of 4 d-slices, 128 bc), 256 threads.
// Thread mapping: wq = tid&15 owns w-range [wq*4, wq*4+4); r0 = tid>>4 is the
// starting row (d,h) index. Row r = r0 + 16*i for i in [0,16). Then:
//   d_local = i>>2 (4 regs), h = r0 + 16*(i&3) (4 regs), w fixed (4 regs).
// All accumulation in registers; block reduction at the end only.
// ---------------------------------------------------------------------------
__global__ void __launch_bounds__(256) reduce_kernel(const float* __restrict__ x) {
    const int bc    = blockIdx.y;     // 0..127
    const int chunk = blockIdx.x;     // 0..15 (4 d-slices each)
    const int tid   = threadIdx.x;
    const int r0 = tid >> 4;          // 0..15
    const int wq = tid & 15;          // float4 column within row

    // bc block = 64*64*64 floats = 65536 float4; chunk = 4*64*64 floats = 4096 float4
    const float4* xb = (const float4*)x + (size_t)bc * 65536 + (size_t)chunk * 4096;

    float aD[4] = {0.f, 0.f, 0.f, 0.f};
    float aH[4] = {0.f, 0.f, 0.f, 0.f};
    float aW[4] = {0.f, 0.f, 0.f, 0.f};
    float ssq = 0.f;

#pragma unroll
    for (int i = 0; i < 16; i++) {
        float4 v = xb[(r0 + 16 * i) * 16 + wq];
        float s = (v.x + v.y) + (v.z + v.w);
        aD[i >> 2] += s;
        aH[i & 3]  += s;
        aW[0] += v.x; aW[1] += v.y; aW[2] += v.z; aW[3] += v.w;
        ssq = fmaf(v.x, v.x, ssq);
        ssq = fmaf(v.y, v.y, ssq);
        ssq = fmaf(v.z, v.z, ssq);
        ssq = fmaf(v.w, v.w, ssq);
    }

    __shared__ float s1[4];
    __shared__ float s2[64];
    __shared__ float s3[64];
    __shared__ float sq;
    if (tid < 64) { s2[tid] = 0.f; s3[tid] = 0.f; }
    if (tid < 4)  s1[tid] = 0.f;
    if (tid == 0) sq = 0.f;
    __syncthreads();

    const unsigned FULL = 0xffffffffu;
    const int lane = tid & 31;

    // aD: identical (d) semantics across all lanes -> full-warp tree
#pragma unroll
    for (int k = 0; k < 4; k++) {
        float v = aD[k];
        v += __shfl_xor_sync(FULL, v, 16);
        v += __shfl_xor_sync(FULL, v, 8);
        v += __shfl_xor_sync(FULL, v, 4);
        v += __shfl_xor_sync(FULL, v, 2);
        v += __shfl_xor_sync(FULL, v, 1);
        if (lane == 0) atomicAdd(&s1[k], v);
    }
    {
        float v = ssq;
        v += __shfl_xor_sync(FULL, v, 16);
        v += __shfl_xor_sync(FULL, v, 8);
        v += __shfl_xor_sync(FULL, v, 4);
        v += __shfl_xor_sync(FULL, v, 2);
        v += __shfl_xor_sync(FULL, v, 1);
        if (lane == 0) atomicAdd(&sq, v);
    }
    // aH: same h within each 16-lane half-warp -> half-warp tree
    const int h0 = tid >> 4;  // 0..15
#pragma unroll
    for (int k = 0; k < 4; k++) {
        float v = aH[k];
        v += __shfl_xor_sync(FULL, v, 8);
        v += __shfl_xor_sync(FULL, v, 4);
        v += __shfl_xor_sync(FULL, v, 2);
        v += __shfl_xor_sync(FULL, v, 1);
        if ((lane & 15) == 0) atomicAdd(&s2[h0 + 16 * k], v);
    }
    // aW: lanes l and l^16 share the same w-group -> fold once
#pragma unroll
    for (int k = 0; k < 4; k++) {
        float v = aW[k];
        v += __shfl_xor_sync(FULL, v, 16);
        if (lane < 16) atomicAdd(&s3[wq * 4 + k], v);
    }
    __syncthreads();

    if (tid < 4)
        atomicAdd(&g_S1[bc * 64 + chunk * 4 + tid], s1[tid]);
    if (tid < 64) {
        atomicAdd(&g_S2[bc * 64 + tid], s2[tid]);
        atomicAdd(&g_S3[bc * 64 + tid], s3[tid]);
    }
    if (tid == 0)
        atomicAdd(&g_SSQ[bc & 15], sq);
}

// ---------------------------------------------------------------------------
// Kernel 2: BN affine correction + three 64->32 projections + erf-GELU.
// One block per bc, 96 threads (one per output element).
// ---------------------------------------------------------------------------
__global__ void __launch_bounds__(96) finalize_kernel(
    const float* __restrict__ gamma, const float* __restrict__ beta,
    const float* __restrict__ core1, const float* __restrict__ core3,
    float* __restrict__ out) {
    const int bc = blockIdx.x;
    const int c  = bc & 15;
    const int b  = bc >> 4;
    const int t  = threadIdx.x;   // 0..95

    __shared__ float red[64];
    __shared__ float sv[192];     // v1[0:64], v2[64:128], v3[128:192]
    __shared__ float s_scale, s_shift;

    // channel sum of x = sum over b' , d of S1
    if (t < 64) {
        float s = 0.f;
#pragma unroll
        for (int bp = 0; bp < 8; bp++) s += g_S1[(bp * 16 + c) * 64 + t];
        red[t] = s;
    }
    __syncthreads();
    if (t == 0) {
        float tot = 0.f;
        for (int i = 0; i < 64; i++) tot += red[i];
        const float N = 8.0f * 262144.0f;   // B*D*H*W
        float mean = tot / N;
        float var  = g_SSQ[c] / N - mean * mean;
        float inv  = rsqrtf(var + EPSV);
        float sc   = gamma[c] * inv;
        s_scale = sc;
        s_shift = beta[c] - mean * sc;
    }
    __syncthreads();

    const float invHW = 1.0f / 4096.0f;   // each S entry is a sum of 64*64 values
    if (t < 64) {
        float sc = s_scale, sh = s_shift;
        sv[t]       = g_S1[bc * 64 + t] * invHW * sc + sh;
        sv[64 + t]  = g_S2[bc * 64 + t] * invHW * sc + sh;
        sv[128 + t] = g_S3[bc * 64 + t] * invHW * sc + sh;
    }
    __syncthreads();

    const int mode = t >> 5;   // 0: m1, 1: m2, 2: m3
    const int r    = t & 31;
    float acc = 0.f;
    if (mode == 0) {
#pragma unroll
        for (int d = 0; d < 64; d++) acc = fmaf(sv[d], core1[d * 32 + r], acc);
    } else if (mode == 1) {
#pragma unroll
        for (int h = 0; h < 64; h++) acc = fmaf(sv[64 + h], g_W2[h * 32 + r], acc);
    } else {
#pragma unroll
        for (int w = 0; w < 64; w++) acc = fmaf(sv[128 + w], core3[r * 64 + w], acc);
    }
    // exact (erf) GELU
    float g = 0.5f * acc * (1.0f + erff(acc * 0.70710678118654752f));
    out[b * 1536 + c * 96 + t] = g;
}

// ---------------------------------------------------------------------------
// kernel_launch
// inputs (metadata order): x, gamma, beta, core1, core2, core3
// ---------------------------------------------------------------------------
extern "C" void kernel_launch(void* const* d_in, const int* in_sizes, int n_in,
                              void* d_out, int out_size) {
    const float* x     = (const float*)d_in[0];
    const float* gamma = (const float*)d_in[1];
    const float* beta  = (const float*)d_in[2];
    const float* core1 = (const float*)d_in[3];
    const float* core2 = (const float*)d_in[4];
    const float* core3 = (const float*)d_in[5];
    float* out = (float*)d_out;

    prep_kernel<<<105, 256>>>(core2);
    reduce_kernel<<<dim3(16, 128), 256>>>(x);
    finalize_kernel<<<128, 96>>>(gamma, beta, core1, core3, out);
}